// round 7
// baseline (speedup 1.0000x reference)
#include <cuda_runtime.h>
#include <cuda_bf16.h>
#include <math.h>

// Problem dims
#define TT 512
#define BB 64
#define II 512
#define HH 512

// Phase-2: 16 clusters x 8 CTAs. Cluster owns 4 batches; CTA owns 64 j.
#define CSZ  8             // cluster size
#define JT   64            // j per CTA
#define BT   4             // batches per cluster
#define HSTR 520           // h_sh row stride (floats)
#define RSTR 17            // reduction row stride (floats)

// ---- f32x2 helpers -------------------------------------------------------
__device__ __forceinline__ unsigned long long pack2(float x, float y) {
    unsigned long long r;
    asm("mov.b64 %0, {%1, %2};" : "=l"(r) : "f"(x), "f"(y));
    return r;
}
__device__ __forceinline__ float hadd2(unsigned long long v) {
    float lo, hi;
    asm("mov.b64 {%0, %1}, %2;" : "=f"(lo), "=f"(hi) : "l"(v));
    return lo + hi;
}
#define FMA2(c, a, b) \
    asm("fma.rn.f32x2 %0, %1, %2, %3;" : "=l"(c) : "l"(a), "l"(b), "l"(c))

__device__ __forceinline__ unsigned smem_u32(const void* p) {
    unsigned a;
    asm("{ .reg .u64 t; cvta.to.shared.u64 t, %1; cvt.u32.u64 %0, t; }"
        : "=r"(a) : "l"(p));
    return a;
}
__device__ __forceinline__ unsigned mapa_u32(unsigned addr, unsigned rank) {
    unsigned r;
    asm("mapa.shared::cluster.u32 %0, %1, %2;" : "=r"(r) : "r"(addr), "r"(rank));
    return r;
}
__device__ __forceinline__ void mbar_wait_acq_cluster(unsigned addr, unsigned parity) {
    asm volatile(
        "{\n\t"
        ".reg .pred P;\n\t"
        "W_%=:\n\t"
        "mbarrier.try_wait.parity.acquire.cluster.shared::cta.b64 P, [%0], %1, 0x989680;\n\t"
        "@P bra.uni D_%=;\n\t"
        "bra.uni W_%=;\n\t"
        "D_%=:\n\t"
        "}"
        :: "r"(addr), "r"(parity) : "memory");
}

// ---------------------------------------------------------------------------
// Phase 1: xp = X @ W^T  (M=32768, N=512, K=512), 128x128 tile, 8x8 micro.
// ---------------------------------------------------------------------------
__global__ void __launch_bounds__(256) gemm_xp_kernel(
    const float* __restrict__ X, const float* __restrict__ W,
    float* __restrict__ C)
{
    const int K = II, N = HH;
    __shared__ __align__(16) float As[16][128];
    __shared__ __align__(16) float Bs[16][128];

    const int bm = blockIdx.x * 128;
    const int bn = blockIdx.y * 128;
    const int tid = threadIdx.x;
    const int tx = tid & 15;
    const int ty = tid >> 4;

    float acc[8][8];
#pragma unroll
    for (int i = 0; i < 8; i++)
#pragma unroll
        for (int j = 0; j < 8; j++) acc[i][j] = 0.0f;

    for (int k0 = 0; k0 < K; k0 += 16) {
#pragma unroll
        for (int l = 0; l < 2; l++) {
            int idx = tid + l * 256;
            int r = idx >> 2;
            int c = (idx & 3) * 4;
            float4 va = *(const float4*)&X[(size_t)(bm + r) * K + k0 + c];
            As[c + 0][r] = va.x; As[c + 1][r] = va.y;
            As[c + 2][r] = va.z; As[c + 3][r] = va.w;
            float4 vb = *(const float4*)&W[(size_t)(bn + r) * K + k0 + c];
            Bs[c + 0][r] = vb.x; Bs[c + 1][r] = vb.y;
            Bs[c + 2][r] = vb.z; Bs[c + 3][r] = vb.w;
        }
        __syncthreads();

#pragma unroll
        for (int kk = 0; kk < 16; kk++) {
            float a[8], b[8];
            *(float4*)&a[0] = *(const float4*)&As[kk][ty * 8];
            *(float4*)&a[4] = *(const float4*)&As[kk][ty * 8 + 4];
            *(float4*)&b[0] = *(const float4*)&Bs[kk][tx * 8];
            *(float4*)&b[4] = *(const float4*)&Bs[kk][tx * 8 + 4];
#pragma unroll
            for (int i = 0; i < 8; i++)
#pragma unroll
                for (int j = 0; j < 8; j++)
                    acc[i][j] = fmaf(a[i], b[j], acc[i][j]);
        }
        __syncthreads();
    }

#pragma unroll
    for (int i = 0; i < 8; i++) {
        int row = bm + ty * 8 + i;
        float4 v0 = make_float4(acc[i][0], acc[i][1], acc[i][2], acc[i][3]);
        float4 v1 = make_float4(acc[i][4], acc[i][5], acc[i][6], acc[i][7]);
        *(float4*)&C[(size_t)row * N + bn + tx * 8]     = v0;
        *(float4*)&C[(size_t)row * N + bn + tx * 8 + 4] = v1;
    }
}

// ---------------------------------------------------------------------------
// Phase 2: persistent recurrence over 8-CTA clusters with DSMEM h exchange.
//   cluster = blockIdx.x>>3 (b0 = cluster*4), rank = ctarank (j0 = rank*64).
//   Thread (jp = tid&15, ks = tid>>4): W rows j0+jp*4+jj (jj 0..3), k in
//   [ks*32, ks*32+32) in registers (f32x2). Computes acc[4jj][4bb].
//   h(t) slices are PUSHED into all 8 CTAs' h_sh via st.shared::cluster,
//   signaled by mbarrier.arrive.release.cluster; consumers try_wait.acquire.
//   h_sh XOR-4 swizzle (bit5 of k flips bit2) -> conflict-free LDS.128.
//   Reduction rows stride 17 (odd): scalar reads, conflict-free both ways.
// ---------------------------------------------------------------------------
__global__ void __launch_bounds__(256, 1) __cluster_dims__(CSZ, 1, 1)
rnn_recurrence_kernel(const float* __restrict__ w_hh,
                      float* __restrict__ out, int has_last)
{
    __shared__ __align__(16) float h_sh[2][BT][HSTR];
    __shared__ __align__(16) float red[256 * RSTR];
    __shared__ __align__(8) unsigned long long mbar[2];

    const int tid = threadIdx.x;
    unsigned rank;
    asm("mov.u32 %0, %%cluster_ctarank;" : "=r"(rank));
    const int b0 = (blockIdx.x >> 3) * BT;
    const int j0 = (int)rank * JT;

    const unsigned hsh_base  = smem_u32(&h_sh[0][0][0]);
    const unsigned mbar_base = smem_u32(&mbar[0]);

    if (tid == 0) {
        asm volatile("mbarrier.init.shared.b64 [%0], %1;"
                     :: "r"(mbar_base), "r"((unsigned)CSZ) : "memory");
        asm volatile("mbarrier.init.shared.b64 [%0], %1;"
                     :: "r"(mbar_base + 8), "r"((unsigned)CSZ) : "memory");
    }
    __syncthreads();

    const int ks = tid >> 4;       // 0..15 (32 k each)
    const int jp = tid & 15;       // 0..15 (4 j each)
    const int kbase = ks * 32;
    const int cxor = (ks & 1) << 2;   // bit3 of k4 = ks bit0 -> flip bit2

    // ---- W slab in registers: wreg[jj][2q+i] = pair of w[j][k]
    unsigned long long wreg[4][16];
#pragma unroll
    for (int jj = 0; jj < 4; jj++) {
        const float* wr = &w_hh[(size_t)(j0 + jp * 4 + jj) * HH + kbase];
#pragma unroll
        for (int q = 0; q < 8; q++) {
            float4 v = *(const float4*)&wr[q * 4];
            wreg[jj][q * 2 + 0] = pack2(v.x, v.y);
            wreg[jj][q * 2 + 1] = pack2(v.z, v.w);
        }
    }

    // barriers initialized in all CTAs before any arrive
    asm volatile("barrier.cluster.arrive.aligned;" ::: "memory");
    asm volatile("barrier.cluster.wait.aligned;" ::: "memory");

    // output mapping: one output per thread
    const int ob = tid >> 6;            // 0..3
    const int oj = tid & 63;            // 0..63
    const int gj = j0 + oj;
    const int gb = b0 + ob;
    // swizzled float index of this output's k-position in a peer's h row
    const int swj = gj ^ (((gj >> 5) & 1) << 2);

    float* __restrict__ hall  = out;
    float* __restrict__ hlast = out + (size_t)TT * BB * HH;

    for (int t = 0; t < TT; t++) {
        float xp = hall[((size_t)t * BB + gb) * HH + gj];   // prefetch

        float hsum = 0.0f;
        if (t > 0) {
            const int s = t - 1;
            mbar_wait_acq_cluster(mbar_base + (unsigned)((s & 1) * 8),
                                  (unsigned)((s >> 1) & 1));

            const float* hb = &h_sh[s & 1][0][0];
            unsigned long long acc[4][4];
#pragma unroll
            for (int jj = 0; jj < 4; jj++)
#pragma unroll
                for (int bb = 0; bb < 4; bb++) acc[jj][bb] = 0ULL;

#pragma unroll
            for (int q = 0; q < 8; q++) {
                const int koff = kbase + ((q * 4) ^ cxor);
#pragma unroll
                for (int bb = 0; bb < 4; bb++) {
                    ulonglong2 hv = *(const ulonglong2*)&hb[bb * HSTR + koff];
#pragma unroll
                    for (int jj = 0; jj < 4; jj++) {
                        FMA2(acc[jj][bb], wreg[jj][q * 2 + 0], hv.x);
                        FMA2(acc[jj][bb], wreg[jj][q * 2 + 1], hv.y);
                    }
                }
            }

            // partials -> red[row][ks], row = bb*64 + jp*4 + jj
#pragma unroll
            for (int jj = 0; jj < 4; jj++)
#pragma unroll
                for (int bb = 0; bb < 4; bb++)
                    red[(bb * 64 + jp * 4 + jj) * RSTR + ks] =
                        hadd2(acc[jj][bb]);
            __syncthreads();

            // scalar reads: row tid, stride 17 -> 17*tid mod 32 covers all
            // banks (17 coprime 32); 4B loads, no alignment requirement.
            const float* rr = &red[tid * RSTR];
            float s0 = 0.f, s1 = 0.f, s2 = 0.f, s3 = 0.f;
#pragma unroll
            for (int i = 0; i < 16; i += 4) {
                s0 += rr[i + 0];
                s1 += rr[i + 1];
                s2 += rr[i + 2];
                s3 += rr[i + 3];
            }
            hsum = (s0 + s1) + (s2 + s3);
        }

        float h = tanhf(xp + hsum);

        if (t != TT - 1) {
            // push own output into all 8 CTAs' h_sh[t&1]
            const unsigned loff = hsh_base +
                (unsigned)((((t & 1) * BT + ob) * HSTR + swj) * 4);
#pragma unroll
            for (unsigned r = 0; r < CSZ; r++) {
                unsigned ra = mapa_u32(loff, r);
                asm volatile("st.shared::cluster.f32 [%0], %1;"
                             :: "r"(ra), "f"(h) : "memory");
            }
            __syncthreads();   // all pushes issued (red also free now)
            if (tid < CSZ) {
                unsigned ra = mapa_u32(mbar_base + (unsigned)((t & 1) * 8),
                                       (unsigned)tid);
                asm volatile(
                    "mbarrier.arrive.release.cluster.shared::cluster.b64 _, [%0];"
                    :: "r"(ra) : "memory");
            }
        }

        hall[((size_t)t * BB + gb) * HH + gj] = h;
        if (has_last && t == TT - 1)
            hlast[(size_t)gb * HH + gj] = h;
    }
}

// ---------------------------------------------------------------------------
extern "C" void kernel_launch(void* const* d_in, const int* in_sizes, int n_in,
                              void* d_out, int out_size) {
    const float* x    = (const float*)d_in[0];   // (T, B, I)
    const float* w_ih = (const float*)d_in[1];   // (H, I)
    const float* w_hh = (const float*)d_in[2];   // (H, H)
    float* out = (float*)d_out;

    dim3 g1((TT * BB) / 128, HH / 128);
    gemm_xp_kernel<<<g1, 256>>>(x, w_ih, out);

    int has_last = (out_size >= TT * BB * HH + BB * HH) ? 1 : 0;
    rnn_recurrence_kernel<<<128, 256>>>(w_hh, out, has_last);
}

// round 8
// speedup vs baseline: 1.0341x; 1.0341x over previous
#include <cuda_runtime.h>
#include <cuda_bf16.h>
#include <math.h>

// Problem dims
#define TT 512
#define BB 64
#define II 512
#define HH 512

// Phase-2: 128 blocks = 8 groups (8 batches) x 16 j-tiles (32 j each).
#define NBLK 128
#define GRPS 8
#define GBLK 16
#define JT   32
#define BT   8
// thread micro-tile: 4j x 8b x 16k, split-k = 32
#define HSTR 520            // h_sh row stride in floats (512 + 8 pad)
#define RSTR 37             // reduction row stride in floats

__device__ __align__(16) float g_hbuf[2 * BB * HH];
__device__ __align__(16) unsigned g_arrive[NBLK];   // zero-init; monotonic

// ---- f32x2 helpers -------------------------------------------------------
__device__ __forceinline__ unsigned long long pack2(float x, float y) {
    unsigned long long r;
    asm("mov.b64 %0, {%1, %2};" : "=l"(r) : "f"(x), "f"(y));
    return r;
}
__device__ __forceinline__ float hadd2(unsigned long long v) {
    float lo, hi;
    asm("mov.b64 {%0, %1}, %2;" : "=f"(lo), "=f"(hi) : "l"(v));
    return lo + hi;
}
__device__ __forceinline__ float2 unpack2(unsigned long long v) {
    float lo, hi;
    asm("mov.b64 {%0, %1}, %2;" : "=f"(lo), "=f"(hi) : "l"(v));
    return make_float2(lo, hi);
}
#define FMA2(c, a, b) \
    asm("fma.rn.f32x2 %0, %1, %2, %3;" : "=l"(c) : "l"(a), "l"(b), "l"(c))

// ---------------------------------------------------------------------------
// Phase 1: xp = X @ W^T  (M=32768, N=512, K=512), 128x128 tile, 8x8 micro,
// f32x2 accumulation: acc2[i][j2] holds the (j2*2, j2*2+1) pair for row i.
// ---------------------------------------------------------------------------
__global__ void __launch_bounds__(256) gemm_xp_kernel(
    const float* __restrict__ X, const float* __restrict__ W,
    float* __restrict__ C)
{
    const int K = II, N = HH;
    __shared__ __align__(16) float As[16][128];
    __shared__ __align__(16) float Bs[16][128];

    const int bm = blockIdx.x * 128;
    const int bn = blockIdx.y * 128;
    const int tid = threadIdx.x;
    const int tx = tid & 15;
    const int ty = tid >> 4;

    unsigned long long acc2[8][4];
#pragma unroll
    for (int i = 0; i < 8; i++)
#pragma unroll
        for (int j = 0; j < 4; j++) acc2[i][j] = 0ULL;

    for (int k0 = 0; k0 < K; k0 += 16) {
#pragma unroll
        for (int l = 0; l < 2; l++) {
            int idx = tid + l * 256;
            int r = idx >> 2;
            int c = (idx & 3) * 4;
            float4 va = *(const float4*)&X[(size_t)(bm + r) * K + k0 + c];
            As[c + 0][r] = va.x; As[c + 1][r] = va.y;
            As[c + 2][r] = va.z; As[c + 3][r] = va.w;
            float4 vb = *(const float4*)&W[(size_t)(bn + r) * K + k0 + c];
            Bs[c + 0][r] = vb.x; Bs[c + 1][r] = vb.y;
            Bs[c + 2][r] = vb.z; Bs[c + 3][r] = vb.w;
        }
        __syncthreads();

#pragma unroll
        for (int kk = 0; kk < 16; kk++) {
            float a[8];
            *(float4*)&a[0] = *(const float4*)&As[kk][ty * 8];
            *(float4*)&a[4] = *(const float4*)&As[kk][ty * 8 + 4];
            // b as 64-bit pairs straight from smem (16B aligned)
            ulonglong2 b01 = *(const ulonglong2*)&Bs[kk][tx * 8];
            ulonglong2 b23 = *(const ulonglong2*)&Bs[kk][tx * 8 + 4];
            unsigned long long bp[4] = {b01.x, b01.y, b23.x, b23.y};
#pragma unroll
            for (int i = 0; i < 8; i++) {
                unsigned long long av = pack2(a[i], a[i]);
#pragma unroll
                for (int j = 0; j < 4; j++)
                    FMA2(acc2[i][j], av, bp[j]);
            }
        }
        __syncthreads();
    }

#pragma unroll
    for (int i = 0; i < 8; i++) {
        int row = bm + ty * 8 + i;
        float2 p0 = unpack2(acc2[i][0]);
        float2 p1 = unpack2(acc2[i][1]);
        float2 p2 = unpack2(acc2[i][2]);
        float2 p3 = unpack2(acc2[i][3]);
        float4 v0 = make_float4(p0.x, p0.y, p1.x, p1.y);
        float4 v1 = make_float4(p2.x, p2.y, p3.x, p3.y);
        *(float4*)&C[(size_t)row * N + bn + tx * 8]     = v0;
        *(float4*)&C[(size_t)row * N + bn + tx * 8 + 4] = v1;
    }
}

// ---------------------------------------------------------------------------
// Phase 2: persistent recurrence (EXACT R5 engine, 1511us measured).
//   W in registers + f32x2 FMA + broadcast h, flat L2 group barriers.
// ---------------------------------------------------------------------------
__global__ void __launch_bounds__(256) rnn_recurrence_kernel(
    const float* __restrict__ w_hh, float* __restrict__ out, int has_last)
{
    extern __shared__ __align__(16) float smem[];
    float* h_sh = smem;                       // [BT][HSTR] = 8 x 520
    float* red  = smem + BT * HSTR;           // [256][RSTR] = 256 x 37

    const int tid = threadIdx.x;
    const int bid = blockIdx.x;
    const int grp = bid >> 4;
    const int jt  = bid & 15;
    const int b0  = grp * BT;
    const int j0  = jt * JT;

    const int ks = tid >> 3;       // 0..31
    const int jp = tid & 7;        // 0..7
    const int kbase = ks * 16;
    // XOR constant for this thread's k-slice: bit3 of k4 (= ks bit1) -> +-4
    const int cxor = (ks & 2) << 1;

    __shared__ unsigned s_base;
    if (tid == 0) s_base = *((volatile unsigned*)&g_arrive[bid]);

    // ---- load W slab into registers: wreg[jj][p] = (w[j][k2p], w[j][k2p+1])
    unsigned long long wreg[4][8];
#pragma unroll
    for (int jj = 0; jj < 4; jj++) {
        const float* wr = &w_hh[(size_t)(j0 + jp * 4 + jj) * HH + kbase];
#pragma unroll
        for (int q = 0; q < 4; q++) {
            float4 v = *(const float4*)&wr[q * 4];
            wreg[jj][q * 2 + 0] = pack2(v.x, v.y);
            wreg[jj][q * 2 + 1] = pack2(v.z, v.w);
        }
    }
    __syncthreads();
    const unsigned base = s_base;

    // output mapping (coalesced): j = o&31, b = o>>5
    const int gj = j0 + (tid & 31);
    const int gb = b0 + (tid >> 5);

    float* __restrict__ hall  = out;
    float* __restrict__ hlast = out + (size_t)TT * BB * HH;

    for (int t = 0; t < TT; t++) {
        // prefetch xp (own slice; no cross-block hazard)
        float xp = hall[((size_t)t * BB + gb) * HH + gj];

        float hsum = 0.0f;
        if (t > 0) {
            // ---- group barrier: wait for all 16 group blocks at step t-1
            if (tid < 32) {
                const unsigned tgt = base + (unsigned)t;
                const unsigned* fl = &g_arrive[grp * GBLK + (tid & 15)];
                for (;;) {
                    unsigned v = (tid < 16) ? __ldcg(fl) : tgt;
                    if (__all_sync(0xffffffffu, v >= tgt)) break;
                    __nanosleep(32);
                }
                __threadfence();
            }
            __syncthreads();

            // ---- stage h(t-1) slice [8 b][512 k] into h_sh (XOR swizzle)
            {
                const int prev = (t - 1) & 1;
                const float4* src = (const float4*)&g_hbuf[
                    (size_t)prev * BB * HH + (size_t)b0 * HH];
#pragma unroll
                for (int r = 0; r < 4; r++) {
                    int idx = tid + r * 256;       // 0..1023
                    int b  = idx >> 7;             // 0..7
                    int k4 = idx & 127;
                    float4 v = __ldcg(&src[(size_t)b * 128 + k4]);
                    int off = b * HSTR + ((k4 * 4) ^ (((k4 >> 3) & 1) << 2));
                    *(float4*)&h_sh[off] = v;
                }
            }
            __syncthreads();

            // ---- compute: acc[jj][bb] over 16 k (f32x2 pairs)
            unsigned long long acc[4][8];
#pragma unroll
            for (int jj = 0; jj < 4; jj++)
#pragma unroll
                for (int bb = 0; bb < 8; bb++) acc[jj][bb] = 0ULL;

#pragma unroll
            for (int q = 0; q < 4; q++) {        // 4 k per q
                const int koff = kbase + ((q * 4) ^ cxor);
#pragma unroll
                for (int bb = 0; bb < 8; bb++) {
                    ulonglong2 hv = *(const ulonglong2*)&h_sh[
                        bb * HSTR + koff];
#pragma unroll
                    for (int jj = 0; jj < 4; jj++) {
                        FMA2(acc[jj][bb], wreg[jj][q * 2 + 0], hv.x);
                        FMA2(acc[jj][bb], wreg[jj][q * 2 + 1], hv.y);
                    }
                }
            }

            // ---- partials -> red[row][ks], row = bb*32 + jp*4 + jj
#pragma unroll
            for (int jj = 0; jj < 4; jj++)
#pragma unroll
                for (int bb = 0; bb < 8; bb++)
                    red[(bb * 32 + jp * 4 + jj) * RSTR + ks] =
                        hadd2(acc[jj][bb]);
            __syncthreads();

            // ---- thread o sums its row (row index == o)
            const float* rr = &red[tid * RSTR];
            float s = 0.0f;
#pragma unroll
            for (int i = 0; i < 32; i++) s += rr[i];
            hsum = s;
        }

        float h = tanhf(xp + hsum);

        // state store first, then signal (hall store off critical path)
        g_hbuf[((size_t)(t & 1) * BB + gb) * HH + gj] = h;

        if (t != TT - 1) {
            __syncthreads();               // all g_hbuf stores issued; red free
            if (tid == 0) {
                __threadfence();
                *((volatile unsigned*)&g_arrive[bid]) = base + 1u + (unsigned)t;
            }
        }

        hall[((size_t)t * BB + gb) * HH + gj] = h;
        if (has_last && t == TT - 1)
            hlast[(size_t)gb * HH + gj] = h;
    }
}

// ---------------------------------------------------------------------------
extern "C" void kernel_launch(void* const* d_in, const int* in_sizes, int n_in,
                              void* d_out, int out_size) {
    const float* x    = (const float*)d_in[0];   // (T, B, I)
    const float* w_ih = (const float*)d_in[1];   // (H, I)
    const float* w_hh = (const float*)d_in[2];   // (H, H)
    float* out = (float*)d_out;

    dim3 g1((TT * BB) / 128, HH / 128);
    gemm_xp_kernel<<<g1, 256>>>(x, w_ih, out);

    int smem_bytes = (BT * HSTR + 256 * RSTR) * (int)sizeof(float); // ~54KB
    cudaFuncSetAttribute(rnn_recurrence_kernel,
                         cudaFuncAttributeMaxDynamicSharedMemorySize, smem_bytes);
    int has_last = (out_size >= TT * BB * HH + BB * HH) ? 1 : 0;
    rnn_recurrence_kernel<<<NBLK, 256, smem_bytes>>>(w_hh, out, has_last);
}